// round 16
// baseline (speedup 1.0000x reference)
#include <cuda_runtime.h>
#include <cuda_fp16.h>
#include <cstdint>

#define KD 128
#define MAXN 100000
#define MAXE 1600000

// ---------------- device scratch (static; no cudaMalloc) --------------------
static __device__ int    g_deg[MAXN];
static __device__ float  g_dinv[MAXN];
static __device__ int    g_rowptr[MAXN + 1];
static __device__ int    g_tmp[MAXN];
static __device__ int    g_bsums[128];
static __device__ int    g_fill[MAXN];
static __device__ int2   g_cedge[MAXE];            // (src, weight-bits)
static __device__ __half g_hA[(size_t)MAXN * KD];  // GEMM outputs (gathered by agg)
static __device__ __half g_hX[(size_t)MAXN * KD];  // agg outputs / GEMM inputs
static __device__ __half g_Wh[3 * 128 * 128 + 64 * 128];  // fp16 W1..W4

// ---------------- cp.async helpers ------------------------------------------
__device__ __forceinline__ void cpa16(uint32_t saddr, const void* gaddr, uint32_t ssz) {
    asm volatile("cp.async.cg.shared.global [%0], [%1], 16, %2;"
                 :: "r"(saddr), "l"(gaddr), "r"(ssz) : "memory");
}
#define CP_COMMIT()  asm volatile("cp.async.commit_group;" ::: "memory")
#define CP_WAIT1()   asm volatile("cp.async.wait_group 1;" ::: "memory")
#define CP_WAIT0()   asm volatile("cp.async.wait_group 0;" ::: "memory")

__device__ __forceinline__ void ldsm4(uint32_t& r0, uint32_t& r1, uint32_t& r2, uint32_t& r3,
                                      uint32_t addr) {
    asm volatile("ldmatrix.sync.aligned.m8n8.x4.shared.b16 {%0,%1,%2,%3}, [%4];"
                 : "=r"(r0), "=r"(r1), "=r"(r2), "=r"(r3) : "r"(addr));
}

// ---------------- preprocessing kernels -------------------------------------
__global__ void k_zero(int n) {
    int i = blockIdx.x * blockDim.x + threadIdx.x;
    if (i < n) { g_deg[i] = 0; g_fill[i] = 0; }
}
__global__ void k_deg(const int* __restrict__ dst, int E) {
    int e = blockIdx.x * blockDim.x + threadIdx.x;
    if (e < E) atomicAdd(&g_deg[dst[e]], 1);
}
__global__ void k_scan1(int n) {
    __shared__ int s[1024];
    int t = threadIdx.x;
    int i = blockIdx.x * 1024 + t;
    int v = (i < n) ? g_deg[i] : 0;
    s[t] = v;
    __syncthreads();
    for (int off = 1; off < 1024; off <<= 1) {
        int x = (t >= off) ? s[t - off] : 0;
        __syncthreads();
        s[t] += x;
        __syncthreads();
    }
    if (i < n) g_tmp[i] = s[t];
    if (t == 1023) g_bsums[blockIdx.x] = s[t];
}
__global__ void k_scan3(int n, int nb) {
    __shared__ int s[128];
    int t = threadIdx.x;
    if (t < 128) s[t] = (t < nb) ? g_bsums[t] : 0;
    __syncthreads();
    for (int off = 1; off < 128; off <<= 1) {
        int x = (t >= off && t < 128) ? s[t - off] : 0;
        __syncthreads();
        if (t < 128) s[t] += x;
        __syncthreads();
    }
    int i = blockIdx.x * blockDim.x + t;
    if (i < n) {
        int grp = i >> 10;
        int offv = (grp == 0) ? 0 : s[grp - 1];
        g_rowptr[i + 1] = g_tmp[i] + offv;
        if (i == 0) g_rowptr[0] = 0;
        int d = g_deg[i];
        g_dinv[i] = (d > 0) ? rsqrtf((float)d) : 0.f;
    }
}
__global__ void k_fill(const int* __restrict__ src, const int* __restrict__ dst, int E) {
    int e = blockIdx.x * blockDim.x + threadIdx.x;
    if (e < E) {
        int s = src[e], d = dst[e];
        int pos = g_rowptr[d] + atomicAdd(&g_fill[d], 1);
        g_cedge[pos] = make_int2(s, __float_as_int(g_dinv[s] * g_dinv[d]));
    }
}

// convert x to fp16
__global__ void k_half_x(const float* __restrict__ in, __half* __restrict__ out, int m4) {
    int i = blockIdx.x * blockDim.x + threadIdx.x;
    if (i < m4) {
        float4 v = ((const float4*)in)[i];
        __half2 h0 = __floats2half2_rn(v.x, v.y);
        __half2 h1 = __floats2half2_rn(v.z, v.w);
        uint2 u;
        u.x = *reinterpret_cast<uint32_t*>(&h0);
        u.y = *reinterpret_cast<uint32_t*>(&h1);
        ((uint2*)out)[i] = u;
    }
}

// convert all 4 weight matrices to fp16
__global__ void k_half_w(const float* __restrict__ W1, const float* __restrict__ W2,
                         const float* __restrict__ W3, const float* __restrict__ W4) {
    int i = blockIdx.x * blockDim.x + threadIdx.x;     // float4 index
    const int S = 128 * 128 / 4;
    const float4* src;
    int off;
    if      (i < S)     { src = (const float4*)W1; off = 0;     }
    else if (i < 2 * S) { src = (const float4*)W2; off = S;     i -= S; }
    else if (i < 3 * S) { src = (const float4*)W3; off = 2 * S; i -= 2 * S; }
    else if (i < 3 * S + S / 2) { src = (const float4*)W4; off = 3 * S; i -= 3 * S; }
    else return;
    float4 v = src[i];
    __half2 h0 = __floats2half2_rn(v.x, v.y);
    __half2 h1 = __floats2half2_rn(v.z, v.w);
    uint2 u;
    u.x = *reinterpret_cast<uint32_t*>(&h0);
    u.y = *reinterpret_cast<uint32_t*>(&h1);
    ((uint2*)g_Wh)[off + i] = u;
}

// ---------------- fp16 mma.sync GEMM (f32 accum), fp16 in/out ---------------
__device__ __forceinline__ void mma_f16(float& d0, float& d1, float& d2, float& d3,
                                        uint32_t a0, uint32_t a1, uint32_t a2, uint32_t a3,
                                        uint32_t b0, uint32_t b1) {
    asm volatile(
        "mma.sync.aligned.m16n8k16.row.col.f32.f16.f16.f32 "
        "{%0,%1,%2,%3}, {%4,%5,%6,%7}, {%8,%9}, {%0,%1,%2,%3};"
        : "+f"(d0), "+f"(d1), "+f"(d2), "+f"(d3)
        : "r"(a0), "r"(a1), "r"(a2), "r"(a3), "r"(b0), "r"(b1));
}

// measured-best config: 256 threads = 8 warps (4m x 2n), CTA tile 128 x O,
// K=128 in 2 chunks of 64 halves, cp.async double-buffered, SKH=72.
template <int O>
__global__ void __launch_bounds__(256, 2) k_mma(const __half* __restrict__ X,
                                                const __half* __restrict__ W,
                                                __half* __restrict__ Y, int n) {
    constexpr int SKH = 72;              // 64 + 8 pad (halves)
    constexpr int NT  = (O / 2) / 8;     // 8 (O=128) or 4 (O=64)
    constexpr int NP  = NT / 2;
    extern __shared__ __half smh[];
    __half* As = smh;                    // [2][128*SKH]
    __half* Bs = smh + 2 * 128 * SKH;    // [2][O*SKH]
    const uint32_t sA = (uint32_t)__cvta_generic_to_shared(As);
    const uint32_t sB = (uint32_t)__cvta_generic_to_shared(Bs);

    const int tid = threadIdx.x;
    const int m0  = blockIdx.x * 128;

    auto load_chunk = [&](int c, int buf) {
        for (int idx = tid; idx < 128 * 8; idx += 256) {
            int row = idx >> 3, seg = idx & 7;
            uint32_t sa = sA + (uint32_t)((buf * 128 * SKH + row * SKH + seg * 8) * 2);
            int grow = (m0 + row < n) ? (m0 + row) : 0;
            const __half* g = X + (size_t)grow * 128 + c * 64 + seg * 8;
            cpa16(sa, g, (m0 + row < n) ? 16u : 0u);
        }
        for (int idx = tid; idx < O * 8; idx += 256) {
            int row = idx >> 3, seg = idx & 7;
            uint32_t sa = sB + (uint32_t)((buf * O * SKH + row * SKH + seg * 8) * 2);
            const __half* g = W + (size_t)row * 128 + c * 64 + seg * 8;
            cpa16(sa, g, 16u);
        }
        CP_COMMIT();
    };

    const int wid  = tid >> 5;
    const int lane = tid & 31;
    const int wm   = (wid & 3) * 32;
    const int wn   = (wid >> 2) * (O / 2);
    const int gid  = lane >> 2;
    const int ctg  = lane & 3;

    uint32_t aoff[2];
#pragma unroll
    for (int mt = 0; mt < 2; mt++) {
        int row = wm + mt * 16 + (lane & 7) + ((lane >> 3) & 1) * 8;
        int kh  = ((lane >> 4) & 1) * 8;
        aoff[mt] = (uint32_t)(row * SKH + kh);
    }
    uint32_t boff[NP];
#pragma unroll
    for (int p = 0; p < NP; p++) {
        int row = wn + (2 * p + ((lane >> 4) & 1)) * 8 + (lane & 7);
        int kh  = ((lane >> 3) & 1) * 8;
        boff[p] = (uint32_t)(row * SKH + kh);
    }

    float acc[2][NT][4];
#pragma unroll
    for (int i = 0; i < 2; i++)
#pragma unroll
        for (int j = 0; j < NT; j++)
#pragma unroll
            for (int c = 0; c < 4; c++) acc[i][j][c] = 0.f;

    load_chunk(0, 0);

#pragma unroll
    for (int c = 0; c < 2; c++) {
        if (c == 0) { load_chunk(1, 1); CP_WAIT1(); }
        else        { CP_WAIT0(); }
        __syncthreads();

        const uint32_t baseA = sA + (uint32_t)(c * 128 * SKH * 2);
        const uint32_t baseB = sB + (uint32_t)(c * O * SKH * 2);
#pragma unroll
        for (int kk = 0; kk < 64; kk += 16) {
            uint32_t a[2][4];
#pragma unroll
            for (int mt = 0; mt < 2; mt++)
                ldsm4(a[mt][0], a[mt][1], a[mt][2], a[mt][3],
                      baseA + (aoff[mt] + kk) * 2);
            uint32_t b[NP][4];
#pragma unroll
            for (int p = 0; p < NP; p++)
                ldsm4(b[p][0], b[p][1], b[p][2], b[p][3],
                      baseB + (boff[p] + kk) * 2);
#pragma unroll
            for (int p = 0; p < NP; p++) {
#pragma unroll
                for (int half = 0; half < 2; half++) {
                    int nt = 2 * p + half;
                    uint32_t b0 = b[p][half * 2], b1 = b[p][half * 2 + 1];
#pragma unroll
                    for (int mt = 0; mt < 2; mt++)
                        mma_f16(acc[mt][nt][0], acc[mt][nt][1], acc[mt][nt][2], acc[mt][nt][3],
                                a[mt][0], a[mt][1], a[mt][2], a[mt][3], b0, b1);
                }
            }
        }
        __syncthreads();
    }

#pragma unroll
    for (int mt = 0; mt < 2; mt++) {
        int r0 = m0 + wm + mt * 16 + gid;
        int r1 = r0 + 8;
#pragma unroll
        for (int nt = 0; nt < NT; nt++) {
            int col = wn + nt * 8 + 2 * ctg;
            if (r0 < n)
                *(__half2*)&Y[(size_t)r0 * O + col] =
                    __floats2half2_rn(acc[mt][nt][0], acc[mt][nt][1]);
            if (r1 < n)
                *(__half2*)&Y[(size_t)r1 * O + col] =
                    __floats2half2_rn(acc[mt][nt][2], acc[mt][nt][3]);
        }
    }
}

// ---------------- aggregation (wide uint4 gathers, MLP=8) --------------------
// agg128: one warp per node; 16 lanes per row, 2 edges per uint4 LDG.
// Main loop: 16-edge groups with all 8 LDGs issued before any FMA (MLP 8).
__global__ void k_agg128(const __half* __restrict__ h, const float* __restrict__ bias,
                         __half* __restrict__ out, int n) {
    int w    = (blockIdx.x * blockDim.x + threadIdx.x) >> 5;
    int lane = threadIdx.x & 31;
    if (w >= n) return;
    const uint4* hv = (const uint4*)h;       // row = 16 uint4
    const int sub = lane >> 4;               // 0,1: which edge of the pair
    const int lq  = lane & 15;               // 16B chunk within the row
    float acc[8];
#pragma unroll
    for (int i = 0; i < 8; i++) acc[i] = 0.f;
    int beg = __ldg(&g_rowptr[w]), end = __ldg(&g_rowptr[w + 1]);

    for (int base = beg; base < end; base += 32) {
        int cnt = end - base;
        if (cnt > 32) cnt = 32;
        int2 rec = make_int2(0, 0);          // zero pad => src 0, weight 0
        if (lane < cnt) rec = __ldg(&g_cedge[base + lane]);
        int j = 0;
        // 16-edge groups: 8 LDGs in flight before FMAs
        for (; j + 16 <= cnt; j += 16) {
            int   s[8];
            float wv[8];
#pragma unroll
            for (int k = 0; k < 8; k++) {
                int idx = j + 2 * k + sub;
                s[k]  = __shfl_sync(0xFFFFFFFFu, rec.x, idx);
                wv[k] = __int_as_float(__shfl_sync(0xFFFFFFFFu, rec.y, idx));
            }
            uint4 v[8];
#pragma unroll
            for (int k = 0; k < 8; k++) v[k] = __ldg(&hv[(size_t)s[k] * 16 + lq]);
#pragma unroll
            for (int k = 0; k < 8; k++) {
                float2 f0 = __half22float2(*reinterpret_cast<__half2*>(&v[k].x));
                float2 f1 = __half22float2(*reinterpret_cast<__half2*>(&v[k].y));
                float2 f2 = __half22float2(*reinterpret_cast<__half2*>(&v[k].z));
                float2 f3 = __half22float2(*reinterpret_cast<__half2*>(&v[k].w));
                acc[0] = fmaf(wv[k], f0.x, acc[0]);
                acc[1] = fmaf(wv[k], f0.y, acc[1]);
                acc[2] = fmaf(wv[k], f1.x, acc[2]);
                acc[3] = fmaf(wv[k], f1.y, acc[3]);
                acc[4] = fmaf(wv[k], f2.x, acc[4]);
                acc[5] = fmaf(wv[k], f2.y, acc[5]);
                acc[6] = fmaf(wv[k], f3.x, acc[6]);
                acc[7] = fmaf(wv[k], f3.y, acc[7]);
            }
        }
        // 8-edge group
        for (; j + 8 <= cnt; j += 8) {
            int   s[4];
            float wv[4];
#pragma unroll
            for (int k = 0; k < 4; k++) {
                int idx = j + 2 * k + sub;
                s[k]  = __shfl_sync(0xFFFFFFFFu, rec.x, idx);
                wv[k] = __int_as_float(__shfl_sync(0xFFFFFFFFu, rec.y, idx));
            }
            uint4 v[4];
#pragma unroll
            for (int k = 0; k < 4; k++) v[k] = __ldg(&hv[(size_t)s[k] * 16 + lq]);
#pragma unroll
            for (int k = 0; k < 4; k++) {
                float2 f0 = __half22float2(*reinterpret_cast<__half2*>(&v[k].x));
                float2 f1 = __half22float2(*reinterpret_cast<__half2*>(&v[k].y));
                float2 f2 = __half22float2(*reinterpret_cast<__half2*>(&v[k].z));
                float2 f3 = __half22float2(*reinterpret_cast<__half2*>(&v[k].w));
                acc[0] = fmaf(wv[k], f0.x, acc[0]);
                acc[1] = fmaf(wv[k], f0.y, acc[1]);
                acc[2] = fmaf(wv[k], f1.x, acc[2]);
                acc[3] = fmaf(wv[k], f1.y, acc[3]);
                acc[4] = fmaf(wv[k], f2.x, acc[4]);
                acc[5] = fmaf(wv[k], f2.y, acc[5]);
                acc[6] = fmaf(wv[k], f3.x, acc[6]);
                acc[7] = fmaf(wv[k], f3.y, acc[7]);
            }
        }
        // pair tail (odd edge padded by rec=0)
        for (; j < cnt; j += 2) {
            int idx = j + sub;
            int   s  = __shfl_sync(0xFFFFFFFFu, rec.x, idx);
            float ww = __int_as_float(__shfl_sync(0xFFFFFFFFu, rec.y, idx));
            uint4 v = __ldg(&hv[(size_t)s * 16 + lq]);
            float2 f0 = __half22float2(*reinterpret_cast<__half2*>(&v.x));
            float2 f1 = __half22float2(*reinterpret_cast<__half2*>(&v.y));
            float2 f2 = __half22float2(*reinterpret_cast<__half2*>(&v.z));
            float2 f3 = __half22float2(*reinterpret_cast<__half2*>(&v.w));
            acc[0] = fmaf(ww, f0.x, acc[0]);
            acc[1] = fmaf(ww, f0.y, acc[1]);
            acc[2] = fmaf(ww, f1.x, acc[2]);
            acc[3] = fmaf(ww, f1.y, acc[3]);
            acc[4] = fmaf(ww, f2.x, acc[4]);
            acc[5] = fmaf(ww, f2.y, acc[5]);
            acc[6] = fmaf(ww, f3.x, acc[6]);
            acc[7] = fmaf(ww, f3.y, acc[7]);
        }
    }
    // combine the two edge-halves
#pragma unroll
    for (int i = 0; i < 8; i++)
        acc[i] += __shfl_xor_sync(0xFFFFFFFFu, acc[i], 16);

    if (sub == 0) {
        const float4* b4 = (const float4*)(bias + lq * 8);
        float4 bb0 = b4[0], bb1 = b4[1];
        acc[0] = fmaxf(acc[0] + bb0.x, 0.f);
        acc[1] = fmaxf(acc[1] + bb0.y, 0.f);
        acc[2] = fmaxf(acc[2] + bb0.z, 0.f);
        acc[3] = fmaxf(acc[3] + bb0.w, 0.f);
        acc[4] = fmaxf(acc[4] + bb1.x, 0.f);
        acc[5] = fmaxf(acc[5] + bb1.y, 0.f);
        acc[6] = fmaxf(acc[6] + bb1.z, 0.f);
        acc[7] = fmaxf(acc[7] + bb1.w, 0.f);
        __half2 h0 = __floats2half2_rn(acc[0], acc[1]);
        __half2 h1 = __floats2half2_rn(acc[2], acc[3]);
        __half2 h2 = __floats2half2_rn(acc[4], acc[5]);
        __half2 h3 = __floats2half2_rn(acc[6], acc[7]);
        uint4 st;
        st.x = *reinterpret_cast<uint32_t*>(&h0);
        st.y = *reinterpret_cast<uint32_t*>(&h1);
        st.z = *reinterpret_cast<uint32_t*>(&h2);
        st.w = *reinterpret_cast<uint32_t*>(&h3);
        __stcs(&((uint4*)out)[(size_t)w * 16 + lq], st);
    }
}

// agg64: row = 8 uint4; 4 edges per LDG (sub = lane>>3). 16-edge groups =
// 4 LDGs in flight. fp32 output, no relu. Combine via shfl_xor 8 then 16.
__global__ void k_agg64(const __half* __restrict__ h, const float* __restrict__ bias,
                        float* __restrict__ out, int n) {
    int w    = (blockIdx.x * blockDim.x + threadIdx.x) >> 5;
    int lane = threadIdx.x & 31;
    if (w >= n) return;
    const uint4* hv = (const uint4*)h;       // row = 8 uint4
    const int sub = lane >> 3;               // 0..3
    const int lq  = lane & 7;
    float acc[8];
#pragma unroll
    for (int i = 0; i < 8; i++) acc[i] = 0.f;
    int beg = __ldg(&g_rowptr[w]), end = __ldg(&g_rowptr[w + 1]);

    for (int base = beg; base < end; base += 32) {
        int cnt = end - base;
        if (cnt > 32) cnt = 32;
        int2 rec = make_int2(0, 0);
        if (lane < cnt) rec = __ldg(&g_cedge[base + lane]);
        int j = 0;
        // 16-edge groups: 4 LDGs in flight
        for (; j + 16 <= cnt; j += 16) {
            int   s[4];
            float wv[4];
#pragma unroll
            for (int k = 0; k < 4; k++) {
                int idx = j + 4 * k + sub;
                s[k]  = __shfl_sync(0xFFFFFFFFu, rec.x, idx);
                wv[k] = __int_as_float(__shfl_sync(0xFFFFFFFFu, rec.y, idx));
            }
            uint4 v[4];
#pragma unroll
            for (int k = 0; k < 4; k++) v[k] = __ldg(&hv[(size_t)s[k] * 8 + lq]);
#pragma unroll
            for (int k = 0; k < 4; k++) {
                float2 f0 = __half22float2(*reinterpret_cast<__half2*>(&v[k].x));
                float2 f1 = __half22float2(*reinterpret_cast<__half2*>(&v[k].y));
                float2 f2 = __half22float2(*reinterpret_cast<__half2*>(&v[k].z));
                float2 f3 = __half22float2(*reinterpret_cast<__half2*>(&v[k].w));
                acc[0] = fmaf(wv[k], f0.x, acc[0]);
                acc[1] = fmaf(wv[k], f0.y, acc[1]);
                acc[2] = fmaf(wv[k], f1.x, acc[2]);
                acc[3] = fmaf(wv[k], f1.y, acc[3]);
                acc[4] = fmaf(wv[k], f2.x, acc[4]);
                acc[5] = fmaf(wv[k], f2.y, acc[5]);
                acc[6] = fmaf(wv[k], f3.x, acc[6]);
                acc[7] = fmaf(wv[k], f3.y, acc[7]);
            }
        }
        // quad tail (zero-padded)
        for (; j < cnt; j += 4) {
            int idx = j + sub;
            int   s  = __shfl_sync(0xFFFFFFFFu, rec.x, idx);
            float ww = __int_as_float(__shfl_sync(0xFFFFFFFFu, rec.y, idx));
            uint4 v = __ldg(&hv[(size_t)s * 8 + lq]);
            float2 f0 = __half22float2(*reinterpret_cast<__half2*>(&v.x));
            float2 f1 = __half22float2(*reinterpret_cast<__half2*>(&v.y));
            float2 f2 = __half22float2(*reinterpret_cast<__half2*>(&v.z));
            float2 f3 = __half22float2(*reinterpret_cast<__half2*>(&v.w));
            acc[0] = fmaf(ww, f0.x, acc[0]);
            acc[1] = fmaf(ww, f0.y, acc[1]);
            acc[2] = fmaf(ww, f1.x, acc[2]);
            acc[3] = fmaf(ww, f1.y, acc[3]);
            acc[4] = fmaf(ww, f2.x, acc[4]);
            acc[5] = fmaf(ww, f2.y, acc[5]);
            acc[6] = fmaf(ww, f3.x, acc[6]);
            acc[7] = fmaf(ww, f3.y, acc[7]);
        }
    }
#pragma unroll
    for (int i = 0; i < 8; i++) {
        acc[i] += __shfl_xor_sync(0xFFFFFFFFu, acc[i], 8);
        acc[i] += __shfl_xor_sync(0xFFFFFFFFu, acc[i], 16);
    }
    if (sub == 0) {
        const float4* b4 = (const float4*)(bias + lq * 8);
        float4 bb0 = b4[0], bb1 = b4[1];
        float4 o0 = make_float4(acc[0] + bb0.x, acc[1] + bb0.y,
                                acc[2] + bb0.z, acc[3] + bb0.w);
        float4 o1 = make_float4(acc[4] + bb1.x, acc[5] + bb1.y,
                                acc[6] + bb1.z, acc[7] + bb1.w);
        float* yr = out + (size_t)w * 64 + lq * 8;
        __stcs((float4*)yr, o0);
        __stcs((float4*)(yr + 4), o1);
    }
}

// ---------------- launch ------------------------------------------------------
extern "C" void kernel_launch(void* const* d_in, const int* in_sizes, int n_in,
                              void* d_out, int out_size) {
    const float* x  = (const float*)d_in[0];
    const int*   ei = (const int*)d_in[1];
    const float* W1 = (const float*)d_in[2];
    const float* b1 = (const float*)d_in[3];
    const float* W2 = (const float*)d_in[4];
    const float* b2 = (const float*)d_in[5];
    const float* W3 = (const float*)d_in[6];
    const float* b3 = (const float*)d_in[7];
    const float* W4 = (const float*)d_in[8];
    const float* b4 = (const float*)d_in[9];

    const int n = in_sizes[0] / KD;       // 100000
    const int E = in_sizes[1] / 2;        // 1600000
    const int* src = ei;
    const int* dst = ei + E;

    __half *hA, *hX, *Wh;
    cudaGetSymbolAddress((void**)&hA, g_hA);
    cudaGetSymbolAddress((void**)&hX, g_hX);
    cudaGetSymbolAddress((void**)&Wh, g_Wh);
    const __half* W1h = Wh;
    const __half* W2h = Wh + 128 * 128;
    const __half* W3h = Wh + 2 * 128 * 128;
    const __half* W4h = Wh + 3 * 128 * 128;

    const int smem128 = 2 * (128 + 128) * 72 * 2;   // 73728
    const int smem64  = 2 * (128 + 64) * 72 * 2;    // 55296
    cudaFuncSetAttribute(k_mma<128>, cudaFuncAttributeMaxDynamicSharedMemorySize, smem128);
    cudaFuncSetAttribute(k_mma<64>,  cudaFuncAttributeMaxDynamicSharedMemorySize, smem64);

    const int TB = 256;
    int nb_n = (n + TB - 1) / TB;
    int nb_e = (E + TB - 1) / TB;
    int nb_scan = (n + 1023) / 1024;           // <= 128
    int nb_gemm = (n + 127) / 128;             // 128-row tiles
    int nb_agg  = (n * 32 + TB - 1) / TB;
    int m4_x    = n * KD / 4;
    int nb_cx   = (m4_x + TB - 1) / TB;
    int nb_cw   = (3 * 4096 + 2048 + TB - 1) / TB;

    static cudaStream_t s2 = [] {
        cudaStream_t s; cudaStreamCreateWithFlags(&s, cudaStreamNonBlocking); return s;
    }();
    static cudaEvent_t eFork = [] {
        cudaEvent_t e; cudaEventCreateWithFlags(&e, cudaEventDisableTiming); return e;
    }();
    static cudaEvent_t eJoin = [] {
        cudaEvent_t e; cudaEventCreateWithFlags(&e, cudaEventDisableTiming); return e;
    }();

    // fork: CSR chain on s2, concurrent with {x/W convert, GEMM1} on main.
    // k_half_w stays on the main stream: k_mma1 consumes g_Wh (R14 race).
    cudaEventRecord(eFork, 0);
    cudaStreamWaitEvent(s2, eFork, 0);

    k_half_x <<<nb_cx, TB>>>(x, hX, m4_x);                 // main
    k_half_w <<<nb_cw, TB>>>(W1, W2, W3, W4);              // main (before mma1!)
    k_zero   <<<nb_n, TB, 0, s2>>>(n);                     // s2
    k_mma<128><<<nb_gemm, 256, smem128>>>(hX, W1h, hA, n); // main (capture slot 3)
    k_deg    <<<nb_e, TB, 0, s2>>>(dst, E);                // s2
    k_scan1  <<<nb_scan, 1024, 0, s2>>>(n);                // s2
    k_scan3  <<<nb_n, TB, 0, s2>>>(n, nb_scan);            // s2
    k_fill   <<<nb_e, TB, 0, s2>>>(src, dst, E);           // s2

    // join: agg1 needs both GEMM1 (main) and CSR (s2)
    cudaEventRecord(eJoin, s2);
    cudaStreamWaitEvent(0, eJoin, 0);

    // --- layer 1 agg ---
    k_agg128  <<<nb_agg, TB>>>(hA, b1, hX, n);
    // --- layer 2 ---
    k_mma<128><<<nb_gemm, 256, smem128>>>(hX, W2h, hA, n);
    k_agg128  <<<nb_agg, TB>>>(hA, b2, hX, n);
    // --- layer 3 ---
    k_mma<128><<<nb_gemm, 256, smem128>>>(hX, W3h, hA, n);
    k_agg128  <<<nb_agg, TB>>>(hA, b3, hX, n);
    // --- layer 4 ---
    k_mma<64> <<<nb_gemm, 256, smem64>>>(hX, W4h, hA, n);
    k_agg64   <<<nb_agg, TB>>>(hA, b4, (float*)d_out, n);
}

// round 17
// speedup vs baseline: 1.0594x; 1.0594x over previous
#include <cuda_runtime.h>
#include <cuda_fp16.h>
#include <cstdint>

#define KD 128
#define MAXN 100000
#define MAXE 1600000

// ---------------- device scratch (static; no cudaMalloc) --------------------
static __device__ int    g_deg[MAXN];
static __device__ float  g_dinv[MAXN];
static __device__ int    g_rowptr[MAXN + 1];
static __device__ int    g_tmp[MAXN];
static __device__ int    g_bsums[128];
static __device__ int    g_fill[MAXN];
static __device__ int2   g_cedge[MAXE];            // (src, weight-bits)
static __device__ __half g_hA[(size_t)MAXN * KD];  // GEMM outputs (gathered by agg)
static __device__ __half g_hX[(size_t)MAXN * KD];  // agg outputs / GEMM inputs
static __device__ __half g_Wh[3 * 128 * 128 + 64 * 128];  // fp16 W1..W4

// ---------------- cp.async helpers ------------------------------------------
__device__ __forceinline__ void cpa16(uint32_t saddr, const void* gaddr, uint32_t ssz) {
    asm volatile("cp.async.cg.shared.global [%0], [%1], 16, %2;"
                 :: "r"(saddr), "l"(gaddr), "r"(ssz) : "memory");
}
#define CP_COMMIT()  asm volatile("cp.async.commit_group;" ::: "memory")
#define CP_WAIT1()   asm volatile("cp.async.wait_group 1;" ::: "memory")
#define CP_WAIT0()   asm volatile("cp.async.wait_group 0;" ::: "memory")

__device__ __forceinline__ void ldsm4(uint32_t& r0, uint32_t& r1, uint32_t& r2, uint32_t& r3,
                                      uint32_t addr) {
    asm volatile("ldmatrix.sync.aligned.m8n8.x4.shared.b16 {%0,%1,%2,%3}, [%4];"
                 : "=r"(r0), "=r"(r1), "=r"(r2), "=r"(r3) : "r"(addr));
}

// ---------------- preprocessing kernels -------------------------------------
__global__ void k_zero(int n) {
    int i = blockIdx.x * blockDim.x + threadIdx.x;
    if (i < n) { g_deg[i] = 0; g_fill[i] = 0; }
}
__global__ void k_deg(const int* __restrict__ dst, int E) {
    int e = blockIdx.x * blockDim.x + threadIdx.x;
    if (e < E) atomicAdd(&g_deg[dst[e]], 1);
}
__global__ void k_scan1(int n) {
    __shared__ int s[1024];
    int t = threadIdx.x;
    int i = blockIdx.x * 1024 + t;
    int v = (i < n) ? g_deg[i] : 0;
    s[t] = v;
    __syncthreads();
    for (int off = 1; off < 1024; off <<= 1) {
        int x = (t >= off) ? s[t - off] : 0;
        __syncthreads();
        s[t] += x;
        __syncthreads();
    }
    if (i < n) g_tmp[i] = s[t];
    if (t == 1023) g_bsums[blockIdx.x] = s[t];
}
__global__ void k_scan3(int n, int nb) {
    __shared__ int s[128];
    int t = threadIdx.x;
    if (t < 128) s[t] = (t < nb) ? g_bsums[t] : 0;
    __syncthreads();
    for (int off = 1; off < 128; off <<= 1) {
        int x = (t >= off && t < 128) ? s[t - off] : 0;
        __syncthreads();
        if (t < 128) s[t] += x;
        __syncthreads();
    }
    int i = blockIdx.x * blockDim.x + t;
    if (i < n) {
        int grp = i >> 10;
        int offv = (grp == 0) ? 0 : s[grp - 1];
        g_rowptr[i + 1] = g_tmp[i] + offv;
        if (i == 0) g_rowptr[0] = 0;
        int d = g_deg[i];
        g_dinv[i] = (d > 0) ? rsqrtf((float)d) : 0.f;
    }
}
__global__ void k_fill(const int* __restrict__ src, const int* __restrict__ dst, int E) {
    int e = blockIdx.x * blockDim.x + threadIdx.x;
    if (e < E) {
        int s = src[e], d = dst[e];
        int pos = g_rowptr[d] + atomicAdd(&g_fill[d], 1);
        g_cedge[pos] = make_int2(s, __float_as_int(g_dinv[s] * g_dinv[d]));
    }
}

// convert all 4 weight matrices to fp16
__global__ void k_half_w(const float* __restrict__ W1, const float* __restrict__ W2,
                         const float* __restrict__ W3, const float* __restrict__ W4) {
    int i = blockIdx.x * blockDim.x + threadIdx.x;     // float4 index
    const int S = 128 * 128 / 4;
    const float4* src;
    int off;
    if      (i < S)     { src = (const float4*)W1; off = 0;     }
    else if (i < 2 * S) { src = (const float4*)W2; off = S;     i -= S; }
    else if (i < 3 * S) { src = (const float4*)W3; off = 2 * S; i -= 2 * S; }
    else if (i < 3 * S + S / 2) { src = (const float4*)W4; off = 3 * S; i -= 3 * S; }
    else return;
    float4 v = src[i];
    __half2 h0 = __floats2half2_rn(v.x, v.y);
    __half2 h1 = __floats2half2_rn(v.z, v.w);
    uint2 u;
    u.x = *reinterpret_cast<uint32_t*>(&h0);
    u.y = *reinterpret_cast<uint32_t*>(&h1);
    ((uint2*)g_Wh)[off + i] = u;
}

// ---------------- fp16 mma.sync GEMM (f32 accum), fp16 out ------------------
// XF32=true: A read directly from fp32 (converted inline) — used for layer 1,
// eliminating the standalone x->fp16 pass. B always fp16 via cp.async.
__device__ __forceinline__ void mma_f16(float& d0, float& d1, float& d2, float& d3,
                                        uint32_t a0, uint32_t a1, uint32_t a2, uint32_t a3,
                                        uint32_t b0, uint32_t b1) {
    asm volatile(
        "mma.sync.aligned.m16n8k16.row.col.f32.f16.f16.f32 "
        "{%0,%1,%2,%3}, {%4,%5,%6,%7}, {%8,%9}, {%0,%1,%2,%3};"
        : "+f"(d0), "+f"(d1), "+f"(d2), "+f"(d3)
        : "r"(a0), "r"(a1), "r"(a2), "r"(a3), "r"(b0), "r"(b1));
}

template <int O, bool XF32>
__global__ void __launch_bounds__(256, 2) k_mma(const void* __restrict__ Xv,
                                                const __half* __restrict__ W,
                                                __half* __restrict__ Y, int n) {
    constexpr int SKH = 72;              // 64 + 8 pad (halves)
    constexpr int NT  = (O / 2) / 8;     // 8 (O=128) or 4 (O=64)
    constexpr int NP  = NT / 2;
    extern __shared__ __half smh[];
    __half* As = smh;                    // [2][128*SKH]
    __half* Bs = smh + 2 * 128 * SKH;    // [2][O*SKH]
    const uint32_t sA = (uint32_t)__cvta_generic_to_shared(As);
    const uint32_t sB = (uint32_t)__cvta_generic_to_shared(Bs);

    const int tid = threadIdx.x;
    const int m0  = blockIdx.x * 128;

    auto load_chunk = [&](int c, int buf) {
        if (XF32) {
            const float* Xf = (const float*)Xv;
            // A: 128 rows x 64 halves; 8 halves (16B) per thread-iter from 8 floats
            for (int idx = tid; idx < 128 * 8; idx += 256) {
                int row = idx >> 3, seg = idx & 7;
                uint32_t off = (uint32_t)((buf * 128 * SKH + row * SKH + seg * 8) * 2);
                uint4 u = make_uint4(0u, 0u, 0u, 0u);
                if (m0 + row < n) {
                    const float4* g = (const float4*)(Xf + (size_t)(m0 + row) * 128 + c * 64 + seg * 8);
                    float4 a = __ldg(g), b = __ldg(g + 1);
                    __half2 p0 = __floats2half2_rn(a.x, a.y);
                    __half2 p1 = __floats2half2_rn(a.z, a.w);
                    __half2 p2 = __floats2half2_rn(b.x, b.y);
                    __half2 p3 = __floats2half2_rn(b.z, b.w);
                    u.x = *reinterpret_cast<uint32_t*>(&p0);
                    u.y = *reinterpret_cast<uint32_t*>(&p1);
                    u.z = *reinterpret_cast<uint32_t*>(&p2);
                    u.w = *reinterpret_cast<uint32_t*>(&p3);
                }
                *(uint4*)((char*)smh + off) = u;
            }
        } else {
            const __half* Xh = (const __half*)Xv;
            for (int idx = tid; idx < 128 * 8; idx += 256) {
                int row = idx >> 3, seg = idx & 7;
                uint32_t sa = sA + (uint32_t)((buf * 128 * SKH + row * SKH + seg * 8) * 2);
                int grow = (m0 + row < n) ? (m0 + row) : 0;
                const __half* g = Xh + (size_t)grow * 128 + c * 64 + seg * 8;
                cpa16(sa, g, (m0 + row < n) ? 16u : 0u);
            }
        }
        for (int idx = tid; idx < O * 8; idx += 256) {
            int row = idx >> 3, seg = idx & 7;
            uint32_t sa = sB + (uint32_t)((buf * O * SKH + row * SKH + seg * 8) * 2);
            const __half* g = W + (size_t)row * 128 + c * 64 + seg * 8;
            cpa16(sa, g, 16u);
        }
        CP_COMMIT();
    };

    const int wid  = tid >> 5;
    const int lane = tid & 31;
    const int wm   = (wid & 3) * 32;
    const int wn   = (wid >> 2) * (O / 2);
    const int gid  = lane >> 2;
    const int ctg  = lane & 3;

    uint32_t aoff[2];
#pragma unroll
    for (int mt = 0; mt < 2; mt++) {
        int row = wm + mt * 16 + (lane & 7) + ((lane >> 3) & 1) * 8;
        int kh  = ((lane >> 4) & 1) * 8;
        aoff[mt] = (uint32_t)(row * SKH + kh);
    }
    uint32_t boff[NP];
#pragma unroll
    for (int p = 0; p < NP; p++) {
        int row = wn + (2 * p + ((lane >> 4) & 1)) * 8 + (lane & 7);
        int kh  = ((lane >> 3) & 1) * 8;
        boff[p] = (uint32_t)(row * SKH + kh);
    }

    float acc[2][NT][4];
#pragma unroll
    for (int i = 0; i < 2; i++)
#pragma unroll
        for (int j = 0; j < NT; j++)
#pragma unroll
            for (int c = 0; c < 4; c++) acc[i][j][c] = 0.f;

    load_chunk(0, 0);

#pragma unroll
    for (int c = 0; c < 2; c++) {
        if (c == 0) { load_chunk(1, 1); CP_WAIT1(); }
        else        { CP_WAIT0(); }
        __syncthreads();

        const uint32_t baseA = sA + (uint32_t)(c * 128 * SKH * 2);
        const uint32_t baseB = sB + (uint32_t)(c * O * SKH * 2);
#pragma unroll
        for (int kk = 0; kk < 64; kk += 16) {
            uint32_t a[2][4];
#pragma unroll
            for (int mt = 0; mt < 2; mt++)
                ldsm4(a[mt][0], a[mt][1], a[mt][2], a[mt][3],
                      baseA + (aoff[mt] + kk) * 2);
            uint32_t b[NP][4];
#pragma unroll
            for (int p = 0; p < NP; p++)
                ldsm4(b[p][0], b[p][1], b[p][2], b[p][3],
                      baseB + (boff[p] + kk) * 2);
#pragma unroll
            for (int p = 0; p < NP; p++) {
#pragma unroll
                for (int half = 0; half < 2; half++) {
                    int nt = 2 * p + half;
                    uint32_t b0 = b[p][half * 2], b1 = b[p][half * 2 + 1];
#pragma unroll
                    for (int mt = 0; mt < 2; mt++)
                        mma_f16(acc[mt][nt][0], acc[mt][nt][1], acc[mt][nt][2], acc[mt][nt][3],
                                a[mt][0], a[mt][1], a[mt][2], a[mt][3], b0, b1);
                }
            }
        }
        __syncthreads();
    }

#pragma unroll
    for (int mt = 0; mt < 2; mt++) {
        int r0 = m0 + wm + mt * 16 + gid;
        int r1 = r0 + 8;
#pragma unroll
        for (int nt = 0; nt < NT; nt++) {
            int col = wn + nt * 8 + 2 * ctg;
            if (r0 < n)
                *(__half2*)&Y[(size_t)r0 * O + col] =
                    __floats2half2_rn(acc[mt][nt][0], acc[mt][nt][1]);
            if (r1 < n)
                *(__half2*)&Y[(size_t)r1 * O + col] =
                    __floats2half2_rn(acc[mt][nt][2], acc[mt][nt][3]);
        }
    }
}

// ---------------- aggregation (R15-exact: wide uint4 gathers, 4 in flight) --
__global__ void k_agg128(const __half* __restrict__ h, const float* __restrict__ bias,
                         __half* __restrict__ out, int n) {
    int w    = (blockIdx.x * blockDim.x + threadIdx.x) >> 5;
    int lane = threadIdx.x & 31;
    if (w >= n) return;
    const uint4* hv = (const uint4*)h;       // row = 16 uint4
    const int sub = lane >> 4;               // 0,1: which edge of the pair
    const int lq  = lane & 15;               // 16B chunk within the row
    float acc[8];
#pragma unroll
    for (int i = 0; i < 8; i++) acc[i] = 0.f;
    int beg = __ldg(&g_rowptr[w]), end = __ldg(&g_rowptr[w + 1]);

    for (int base = beg; base < end; base += 32) {
        int cnt = end - base;
        if (cnt > 32) cnt = 32;
        int2 rec = make_int2(0, 0);          // zero pad => src 0, weight 0
        if (lane < cnt) rec = __ldg(&g_cedge[base + lane]);
        int j = 0;
        for (; j + 8 <= cnt; j += 8) {       // 8 edges per iter, 4 LDG
            int   s[4];
            float wv[4];
#pragma unroll
            for (int k = 0; k < 4; k++) {
                int idx = j + 2 * k + sub;
                s[k]  = __shfl_sync(0xFFFFFFFFu, rec.x, idx);
                wv[k] = __int_as_float(__shfl_sync(0xFFFFFFFFu, rec.y, idx));
            }
            uint4 v[4];
#pragma unroll
            for (int k = 0; k < 4; k++) v[k] = __ldg(&hv[(size_t)s[k] * 16 + lq]);
#pragma unroll
            for (int k = 0; k < 4; k++) {
                float2 f0 = __half22float2(*reinterpret_cast<__half2*>(&v[k].x));
                float2 f1 = __half22float2(*reinterpret_cast<__half2*>(&v[k].y));
                float2 f2 = __half22float2(*reinterpret_cast<__half2*>(&v[k].z));
                float2 f3 = __half22float2(*reinterpret_cast<__half2*>(&v[k].w));
                acc[0] = fmaf(wv[k], f0.x, acc[0]);
                acc[1] = fmaf(wv[k], f0.y, acc[1]);
                acc[2] = fmaf(wv[k], f1.x, acc[2]);
                acc[3] = fmaf(wv[k], f1.y, acc[3]);
                acc[4] = fmaf(wv[k], f2.x, acc[4]);
                acc[5] = fmaf(wv[k], f2.y, acc[5]);
                acc[6] = fmaf(wv[k], f3.x, acc[6]);
                acc[7] = fmaf(wv[k], f3.y, acc[7]);
            }
        }
        for (; j < cnt; j += 2) {            // pair tail (odd edge padded by rec=0)
            int idx = j + sub;
            int   s  = __shfl_sync(0xFFFFFFFFu, rec.x, idx);
            float ww = __int_as_float(__shfl_sync(0xFFFFFFFFu, rec.y, idx));
            uint4 v = __ldg(&hv[(size_t)s * 16 + lq]);
            float2 f0 = __half22float2(*reinterpret_cast<__half2*>(&v.x));
            float2 f1 = __half22float2(*reinterpret_cast<__half2*>(&v.y));
            float2 f2 = __half22float2(*reinterpret_cast<__half2*>(&v.z));
            float2 f3 = __half22float2(*reinterpret_cast<__half2*>(&v.w));
            acc[0] = fmaf(ww, f0.x, acc[0]);
            acc[1] = fmaf(ww, f0.y, acc[1]);
            acc[2] = fmaf(ww, f1.x, acc[2]);
            acc[3] = fmaf(ww, f1.y, acc[3]);
            acc[4] = fmaf(ww, f2.x, acc[4]);
            acc[5] = fmaf(ww, f2.y, acc[5]);
            acc[6] = fmaf(ww, f3.x, acc[6]);
            acc[7] = fmaf(ww, f3.y, acc[7]);
        }
    }
#pragma unroll
    for (int i = 0; i < 8; i++)
        acc[i] += __shfl_xor_sync(0xFFFFFFFFu, acc[i], 16);

    if (sub == 0) {
        const float4* b4 = (const float4*)(bias + lq * 8);
        float4 bb0 = b4[0], bb1 = b4[1];
        acc[0] = fmaxf(acc[0] + bb0.x, 0.f);
        acc[1] = fmaxf(acc[1] + bb0.y, 0.f);
        acc[2] = fmaxf(acc[2] + bb0.z, 0.f);
        acc[3] = fmaxf(acc[3] + bb0.w, 0.f);
        acc[4] = fmaxf(acc[4] + bb1.x, 0.f);
        acc[5] = fmaxf(acc[5] + bb1.y, 0.f);
        acc[6] = fmaxf(acc[6] + bb1.z, 0.f);
        acc[7] = fmaxf(acc[7] + bb1.w, 0.f);
        __half2 h0 = __floats2half2_rn(acc[0], acc[1]);
        __half2 h1 = __floats2half2_rn(acc[2], acc[3]);
        __half2 h2 = __floats2half2_rn(acc[4], acc[5]);
        __half2 h3 = __floats2half2_rn(acc[6], acc[7]);
        uint4 st;
        st.x = *reinterpret_cast<uint32_t*>(&h0);
        st.y = *reinterpret_cast<uint32_t*>(&h1);
        st.z = *reinterpret_cast<uint32_t*>(&h2);
        st.w = *reinterpret_cast<uint32_t*>(&h3);
        __stcs(&((uint4*)out)[(size_t)w * 16 + lq], st);
    }
}

__global__ void k_agg64(const __half* __restrict__ h, const float* __restrict__ bias,
                        float* __restrict__ out, int n) {
    int w    = (blockIdx.x * blockDim.x + threadIdx.x) >> 5;
    int lane = threadIdx.x & 31;
    if (w >= n) return;
    const uint4* hv = (const uint4*)h;       // row = 8 uint4
    const int sub = lane >> 3;               // 0..3
    const int lq  = lane & 7;
    float acc[8];
#pragma unroll
    for (int i = 0; i < 8; i++) acc[i] = 0.f;
    int beg = __ldg(&g_rowptr[w]), end = __ldg(&g_rowptr[w + 1]);

    for (int base = beg; base < end; base += 32) {
        int cnt = end - base;
        if (cnt > 32) cnt = 32;
        int2 rec = make_int2(0, 0);
        if (lane < cnt) rec = __ldg(&g_cedge[base + lane]);
        int j = 0;
        for (; j + 8 <= cnt; j += 8) {       // 8 edges, 2 LDG
#pragma unroll
            for (int k = 0; k < 2; k++) {
                int idx = j + 4 * k + sub;
                int   s  = __shfl_sync(0xFFFFFFFFu, rec.x, idx);
                float ww = __int_as_float(__shfl_sync(0xFFFFFFFFu, rec.y, idx));
                uint4 v = __ldg(&hv[(size_t)s * 8 + lq]);
                float2 f0 = __half22float2(*reinterpret_cast<__half2*>(&v.x));
                float2 f1 = __half22float2(*reinterpret_cast<__half2*>(&v.y));
                float2 f2 = __half22float2(*reinterpret_cast<__half2*>(&v.z));
                float2 f3 = __half22float2(*reinterpret_cast<__half2*>(&v.w));
                acc[0] = fmaf(ww, f0.x, acc[0]);
                acc[1] = fmaf(ww, f0.y, acc[1]);
                acc[2] = fmaf(ww, f1.x, acc[2]);
                acc[3] = fmaf(ww, f1.y, acc[3]);
                acc[4] = fmaf(ww, f2.x, acc[4]);
                acc[5] = fmaf(ww, f2.y, acc[5]);
                acc[6] = fmaf(ww, f3.x, acc[6]);
                acc[7] = fmaf(ww, f3.y, acc[7]);
            }
        }
        for (; j < cnt; j += 4) {            // quad tail, zero-padded
            int idx = j + sub;
            int   s  = __shfl_sync(0xFFFFFFFFu, rec.x, idx);
            float ww = __int_as_float(__shfl_sync(0xFFFFFFFFu, rec.y, idx));
            uint4 v = __ldg(&hv[(size_t)s * 8 + lq]);
            float2 f0 = __half22float2(*reinterpret_cast<__half2*>(&v.x));
            float2 f1 = __half22float2(*reinterpret_cast<__half2*>(&v.y));
            float2 f2 = __half22float2(*reinterpret_cast<__half2*>(&v.z));
            float2 f3 = __half22float2(*reinterpret_cast<__half2*>(&v.w));
            acc[0] = fmaf(ww, f0.x, acc[0]);
            acc[1] = fmaf(ww, f0.y, acc[1]);
            acc[2] = fmaf(ww, f1.x, acc[2]);
            acc[3] = fmaf(ww, f1.y, acc[3]);
            acc[4] = fmaf(ww, f2.x, acc[4]);
            acc[5] = fmaf(ww, f2.y, acc[5]);
            acc[6] = fmaf(ww, f3.x, acc[6]);
            acc[7] = fmaf(ww, f3.y, acc[7]);
        }
    }
#pragma unroll
    for (int i = 0; i < 8; i++) {
        acc[i] += __shfl_xor_sync(0xFFFFFFFFu, acc[i], 8);
        acc[i] += __shfl_xor_sync(0xFFFFFFFFu, acc[i], 16);
    }
    if (sub == 0) {
        const float4* b4 = (const float4*)(bias + lq * 8);
        float4 bb0 = b4[0], bb1 = b4[1];
        float4 o0 = make_float4(acc[0] + bb0.x, acc[1] + bb0.y,
                                acc[2] + bb0.z, acc[3] + bb0.w);
        float4 o1 = make_float4(acc[4] + bb1.x, acc[5] + bb1.y,
                                acc[6] + bb1.z, acc[7] + bb1.w);
        float* yr = out + (size_t)w * 64 + lq * 8;
        __stcs((float4*)yr, o0);
        __stcs((float4*)(yr + 4), o1);
    }
}

// ---------------- launch ------------------------------------------------------
extern "C" void kernel_launch(void* const* d_in, const int* in_sizes, int n_in,
                              void* d_out, int out_size) {
    const float* x  = (const float*)d_in[0];
    const int*   ei = (const int*)d_in[1];
    const float* W1 = (const float*)d_in[2];
    const float* b1 = (const float*)d_in[3];
    const float* W2 = (const float*)d_in[4];
    const float* b2 = (const float*)d_in[5];
    const float* W3 = (const float*)d_in[6];
    const float* b3 = (const float*)d_in[7];
    const float* W4 = (const float*)d_in[8];
    const float* b4 = (const float*)d_in[9];

    const int n = in_sizes[0] / KD;       // 100000
    const int E = in_sizes[1] / 2;        // 1600000
    const int* src = ei;
    const int* dst = ei + E;

    __half *hA, *hX, *Wh;
    cudaGetSymbolAddress((void**)&hA, g_hA);
    cudaGetSymbolAddress((void**)&hX, g_hX);
    cudaGetSymbolAddress((void**)&Wh, g_Wh);
    const __half* W1h = Wh;
    const __half* W2h = Wh + 128 * 128;
    const __half* W3h = Wh + 2 * 128 * 128;
    const __half* W4h = Wh + 3 * 128 * 128;

    const int smem128 = 2 * (128 + 128) * 72 * 2;   // 73728
    const int smem64  = 2 * (128 + 64) * 72 * 2;    // 55296
    cudaFuncSetAttribute((const void*)k_mma<128, true>,
                         cudaFuncAttributeMaxDynamicSharedMemorySize, smem128);
    cudaFuncSetAttribute((const void*)k_mma<128, false>,
                         cudaFuncAttributeMaxDynamicSharedMemorySize, smem128);
    cudaFuncSetAttribute((const void*)k_mma<64, false>,
                         cudaFuncAttributeMaxDynamicSharedMemorySize, smem64);

    const int TB = 256;
    int nb_n = (n + TB - 1) / TB;
    int nb_e = (E + TB - 1) / TB;
    int nb_scan = (n + 1023) / 1024;           // <= 128
    int nb_gemm = (n + 127) / 128;             // 128-row tiles
    int nb_agg  = (n * 32 + TB - 1) / TB;
    int nb_cw   = (3 * 4096 + 2048 + TB - 1) / TB;

    static cudaStream_t s2 = [] {
        cudaStream_t s; cudaStreamCreateWithFlags(&s, cudaStreamNonBlocking); return s;
    }();
    static cudaEvent_t eFork = [] {
        cudaEvent_t e; cudaEventCreateWithFlags(&e, cudaEventDisableTiming); return e;
    }();
    static cudaEvent_t eJoin = [] {
        cudaEvent_t e; cudaEventCreateWithFlags(&e, cudaEventDisableTiming); return e;
    }();

    // fork: CSR chain on s2, concurrent with {W convert, GEMM1(fp32 x)} on main
    cudaEventRecord(eFork, 0);
    cudaStreamWaitEvent(s2, eFork, 0);

    k_half_w <<<nb_cw, TB>>>(W1, W2, W3, W4);              // main (before mma1)
    k_zero   <<<nb_n, TB, 0, s2>>>(n);                     // s2
    k_mma<128, true><<<nb_gemm, 256, smem128>>>(x, W1h, hA, n);  // main
    k_deg    <<<nb_e, TB, 0, s2>>>(dst, E);                // s2
    k_scan1  <<<nb_scan, 1024, 0, s2>>>(n);                // s2
    k_scan3  <<<nb_n, TB, 0, s2>>>(n, nb_scan);            // s2
    k_fill   <<<nb_e, TB, 0, s2>>>(src, dst, E);           // s2

    // join: agg1 needs both GEMM1 (main) and CSR (s2)
    cudaEventRecord(eJoin, s2);
    cudaStreamWaitEvent(0, eJoin, 0);

    // --- layer 1 agg ---
    k_agg128  <<<nb_agg, TB>>>(hA, b1, hX, n);
    // --- layer 2 ---
    k_mma<128, false><<<nb_gemm, 256, smem128>>>(hX, W2h, hA, n);
    k_agg128  <<<nb_agg, TB>>>(hA, b2, hX, n);
    // --- layer 3 ---
    k_mma<128, false><<<nb_gemm, 256, smem128>>>(hX, W3h, hA, n);
    k_agg128  <<<nb_agg, TB>>>(hA, b3, hX, n);
    // --- layer 4 ---
    k_mma<64, false><<<nb_gemm, 256, smem64>>>(hX, W4h, hA, n);
    k_agg64   <<<nb_agg, TB>>>(hA, b4, (float*)d_out, n);
}